// round 12
// baseline (speedup 1.0000x reference)
#include <cuda_runtime.h>
#include <math.h>

// ---------------- problem constants ----------------
#define CB 512      // batch
#define CN 1024     // memory rows
#define CM 128      // memory width
#define CH 512      // hidden
#define CNH 4       // heads
#define EPSC 1e-16f

#define P_STRIDE 536    // 4 * 134
#define Q_STRIDE 1560   // 4 * 390

// ---------------- scratch (allocation-free) ----------------
__device__ float g_mem[(size_t)CB * CN * CM];   // 268 MB working memory state
__device__ float g_inp[CB * 640];
__device__ float g_inp2[CB * 1024];
__device__ float g_gates[CB * 2048];
__device__ float g_P[CB * P_STRIDE];
__device__ float g_Q[CB * Q_STRIDE];
__device__ float g_dotr[CB * CN];
__device__ float g_dotw[CB * CN];
__device__ float g_rnorm[CB * CN];
__device__ float g_partial[CB * 16 * CM];

// ---------------- device helpers ----------------
__device__ __forceinline__ float sigmoidf_(float x) { return 1.f / (1.f + expf(-x)); }
__device__ __forceinline__ float softplusf_(float x) {
    return fmaxf(x, 0.f) + log1pf(expf(-fabsf(x)));
}
__device__ __forceinline__ float warpSum(float v) {
    #pragma unroll
    for (int o = 16; o; o >>= 1) v += __shfl_xor_sync(0xffffffffu, v, o);
    return v;
}
__device__ __forceinline__ float warpMax(float v) {
    #pragma unroll
    for (int o = 16; o; o >>= 1) v = fmaxf(v, __shfl_xor_sync(0xffffffffu, v, o));
    return v;
}
__device__ float blockSum(float v, float* red) {
    int lane = threadIdx.x & 31, w = threadIdx.x >> 5, nw = (blockDim.x + 31) >> 5;
    v = warpSum(v);
    __syncthreads();
    if (lane == 0) red[w] = v;
    __syncthreads();
    if (w == 0) {
        float t = (lane < nw) ? red[lane] : 0.f;
        t = warpSum(t);
        if (lane == 0) red[0] = t;
    }
    __syncthreads();
    return red[0];
}
__device__ float blockMax(float v, float* red) {
    int lane = threadIdx.x & 31, w = threadIdx.x >> 5, nw = (blockDim.x + 31) >> 5;
    v = warpMax(v);
    __syncthreads();
    if (lane == 0) red[w] = v;
    __syncthreads();
    if (w == 0) {
        float t = (lane < nw) ? red[lane] : -INFINITY;
        t = warpMax(t);
        if (lane == 0) red[0] = t;
    }
    __syncthreads();
    return red[0];
}

// ---------------- generic SGEMM: C[M,N] = A[M,K] @ W[N,K]^T (+bias)(+acc)(+sigmoid) ----------------
#define TBM 64
#define TBN 64
#define TBK 16

__global__ void __launch_bounds__(128) sgemm_k(
    float* __restrict__ C, const float* __restrict__ A, const float* __restrict__ W,
    const float* __restrict__ bias, int M, int N, int K, int accFlag, int actFlag)
{
    __shared__ __align__(16) float As[TBK][TBM + 4];
    __shared__ __align__(16) float Bs[TBK][TBN];
    int tid = threadIdx.x;
    int bm = blockIdx.y * TBM;
    int bn = blockIdx.x * TBN;
    int ty = tid >> 4;
    int tx = tid & 15;
    int row0 = ty * 8;
    int col0 = tx * 4;

    float acc[8][4];
    #pragma unroll
    for (int r = 0; r < 8; r++)
        #pragma unroll
        for (int c = 0; c < 4; c++) acc[r][c] = 0.f;

    for (int k0 = 0; k0 < K; k0 += TBK) {
        #pragma unroll
        for (int l = tid; l < TBM * TBK / 4; l += 128) {
            int r = l >> 2;
            int kk = (l & 3) * 4;
            float4 v = *(const float4*)(A + (size_t)(bm + r) * K + k0 + kk);
            As[kk + 0][r] = v.x; As[kk + 1][r] = v.y; As[kk + 2][r] = v.z; As[kk + 3][r] = v.w;
        }
        #pragma unroll
        for (int l = tid; l < TBN * TBK / 4; l += 128) {
            int r = l >> 2;
            int kk = (l & 3) * 4;
            float4 v = make_float4(0.f, 0.f, 0.f, 0.f);
            if (bn + r < N) v = *(const float4*)(W + (size_t)(bn + r) * K + k0 + kk);
            Bs[kk + 0][r] = v.x; Bs[kk + 1][r] = v.y; Bs[kk + 2][r] = v.z; Bs[kk + 3][r] = v.w;
        }
        __syncthreads();
        #pragma unroll
        for (int kk = 0; kk < TBK; kk++) {
            float4 a0 = *(const float4*)&As[kk][row0];
            float4 a1 = *(const float4*)&As[kk][row0 + 4];
            float4 b0 = *(const float4*)&Bs[kk][col0];
            float ar[8] = {a0.x, a0.y, a0.z, a0.w, a1.x, a1.y, a1.z, a1.w};
            float br_[4] = {b0.x, b0.y, b0.z, b0.w};
            #pragma unroll
            for (int r = 0; r < 8; r++)
                #pragma unroll
                for (int c = 0; c < 4; c++) acc[r][c] += ar[r] * br_[c];
        }
        __syncthreads();
    }
    #pragma unroll
    for (int r = 0; r < 8; r++) {
        int gr = bm + row0 + r;
        #pragma unroll
        for (int c = 0; c < 4; c++) {
            int gc = bn + col0 + c;
            if (gc < N) {
                float v = acc[r][c];
                if (bias) v += bias[gc];
                if (accFlag) v += C[(size_t)gr * N + gc];
                if (actFlag) v = sigmoidf_(v);
                C[(size_t)gr * N + gc] = v;
            }
        }
    }
}

// ---------------- small assembly / pointwise kernels ----------------
__global__ void assemble_inp_k(const float* __restrict__ x, const float* __restrict__ pr,
                               float* __restrict__ inp)
{
    int idx = blockIdx.x * blockDim.x + threadIdx.x;
    if (idx >= CB * 640) return;
    int b = idx / 640, j = idx % 640;
    float v;
    if (j < 128) v = x[b * 128 + j];
    else {
        int jj = j - 128;
        v = pr[((jj >> 7) * CB + b) * CM + (jj & 127)];
    }
    inp[idx] = v;
}

__global__ void lstm_k(const float* __restrict__ gates, const float* __restrict__ c0,
                       float* __restrict__ h_out, float* __restrict__ c_out)
{
    int idx = blockIdx.x * blockDim.x + threadIdx.x;
    if (idx >= CB * CH) return;
    int b = idx / CH, j = idx % CH;
    const float* g = gates + (size_t)b * 2048;
    float ig = g[j], fg = g[512 + j], gg = g[1024 + j], og = g[1536 + j];
    float cn = sigmoidf_(fg) * c0[idx] + sigmoidf_(ig) * tanhf(gg);
    float hn = sigmoidf_(og) * tanhf(cn);
    h_out[idx] = hn;
    c_out[idx] = cn;
}

__global__ void assemble_inp2_k(const float* __restrict__ ctrl, const float* __restrict__ rd,
                                float* __restrict__ inp2)
{
    int idx = blockIdx.x * blockDim.x + threadIdx.x;
    if (idx >= CB * 1024) return;
    int b = idx >> 10, j = idx & 1023;
    float v;
    if (j < 512) v = ctrl[b * 512 + j];
    else {
        int jj = j - 512;
        v = rd[(size_t)(jj >> 7) * CB * CM + b * CM + (jj & 127)];
    }
    inp2[idx] = v;
}

// ---------------- head-0 dots + row norms (one stream over prev_mem) ----------------
__global__ void __launch_bounds__(256) dots_k(
    const float* __restrict__ mem, const float* __restrict__ P, const float* __restrict__ Q,
    float* __restrict__ dot_r, float* __restrict__ dot_w, float* __restrict__ rnorm, int head)
{
    int b = blockIdx.x >> 7;
    int n0 = (blockIdx.x & 127) * 8;
    __shared__ __align__(16) float kr[128];
    __shared__ __align__(16) float kw[128];
    int tid = threadIdx.x;
    if (tid < 128) kr[tid] = P[b * P_STRIDE + head * 134 + tid];
    else           kw[tid - 128] = Q[b * Q_STRIDE + head * 390 + (tid - 128)];
    __syncthreads();
    int warp = tid >> 5, lane = tid & 31;
    int n = n0 + warp;
    const float4* row = (const float4*)(mem + ((size_t)b * CN + n) * CM);
    float4 v = row[lane];
    float4 a = *(const float4*)&kr[lane * 4];
    float4 c = *(const float4*)&kw[lane * 4];
    float dr = v.x * a.x + v.y * a.y + v.z * a.z + v.w * a.w;
    float dw = v.x * c.x + v.y * c.y + v.z * c.z + v.w * c.w;
    float ss = v.x * v.x + v.y * v.y + v.z * v.z + v.w * v.w;
    dr = warpSum(dr); dw = warpSum(dw); ss = warpSum(ss);
    if (lane == 0) {
        size_t idx = (size_t)b * CN + n;
        dot_r[idx] = dr;
        dot_w[idx] = dw;
        rnorm[idx] = sqrtf(ss);
    }
}

// ---------------- addressing: softmax / interp / shift / sharpen ----------------
__global__ void __launch_bounds__(256) address_k(
    const float* __restrict__ P, const float* __restrict__ Q,
    const float* __restrict__ dot_r, const float* __restrict__ dot_w,
    const float* __restrict__ rnorm, const float* __restrict__ prev_w,
    float* __restrict__ ws_out, int head)
{
    int b = blockIdx.x & (CB - 1);
    int rw = blockIdx.x >> 9;
    const float* row = (rw == 0) ? (P + b * P_STRIDE + head * 134)
                                 : (Q + b * Q_STRIDE + head * 390);
    const float* dot = ((rw == 0) ? dot_r : dot_w) + (size_t)b * CN;
    const float* rn  = rnorm + (size_t)b * CN;
    int widx = 2 * head + rw;
    const float* wp = prev_w + (size_t)widx * CB * CN + (size_t)b * CN;
    float* wout = ws_out + (size_t)widx * CB * CN + (size_t)b * CN;

    __shared__ float sh[CN];
    __shared__ float red[32];
    __shared__ float sp[8];
    int tid = threadIdx.x;

    float kk = 0.f;
    if (tid < 128) { float kv = row[tid]; kk = kv * kv; }
    kk = blockSum(kk, red);
    if (tid == 0) {
        sp[0] = fmaxf(sqrtf(kk), EPSC);
        sp[1] = softplusf_(row[128]);          // beta
        sp[2] = sigmoidf_(row[129]);           // g
        float s0r = row[130], s1r = row[131], s2r = row[132];
        float mx = fmaxf(s0r, fmaxf(s1r, s2r));
        float e0 = expf(s0r - mx), e1 = expf(s1r - mx), e2 = expf(s2r - mx);
        float es = e0 + e1 + e2;
        sp[3] = e0 / es; sp[4] = e1 / es; sp[5] = e2 / es;
        sp[6] = 1.f + softplusf_(row[133]);    // gamma
    }
    __syncthreads();
    float knorm = sp[0], beta = sp[1], gg = sp[2];
    float s0 = sp[3], s1 = sp[4], s2 = sp[5], gamma = sp[6];

    float sc[4];
    float lmax = -INFINITY;
    #pragma unroll
    for (int j = 0; j < 4; j++) {
        int n = tid + j * 256;
        float rnv = fmaxf(rn[n], EPSC);
        sc[j] = beta * (dot[n] / (rnv * knorm));
        lmax = fmaxf(lmax, sc[j]);
    }
    float mx = blockMax(lmax, red);
    float lsum = 0.f;
    float ev[4];
    #pragma unroll
    for (int j = 0; j < 4; j++) { ev[j] = expf(sc[j] - mx); lsum += ev[j]; }
    float S = blockSum(lsum, red);
    #pragma unroll
    for (int j = 0; j < 4; j++) {
        int n = tid + j * 256;
        float wc = ev[j] / S;
        sh[n] = gg * wc + (1.f - gg) * wp[n];
    }
    __syncthreads();
    float wv[4];
    float lsum2 = 0.f;
    #pragma unroll
    for (int j = 0; j < 4; j++) {
        int n = tid + j * 256;
        float wh = s0 * sh[(n + CN - 1) & (CN - 1)] + s1 * sh[n] + s2 * sh[(n + 1) & (CN - 1)];
        wv[j] = powf(wh, gamma);
        lsum2 += wv[j];
    }
    float T = blockSum(lsum2, red);
    float inv = 1.f / (T + EPSC);
    #pragma unroll
    for (int j = 0; j < 4; j++) {
        int n = tid + j * 256;
        wout[n] = wv[j] * inv;
    }
}

// ---------------- FUSED: memory erase/add + partial read vector + NEXT-head dots ----------------
// NOTE: all head-parameter loads from P/Q are SCALAR — head*134 / head*390 are
// not multiples of 4, so float4 loads there trap with misaligned address.
__global__ void __launch_bounds__(256) update_fused_k(
    const float* __restrict__ src, float* __restrict__ dst,
    const float* __restrict__ P, const float* __restrict__ Q,
    const float* __restrict__ ws, float* __restrict__ partial,
    float* __restrict__ dot_r, float* __restrict__ dot_w, float* __restrict__ rnorm,
    int head, int nextHead)
{
    // grid: CB*16 blocks, 256 threads = 8 warps, 64 rows per block (8 per warp)
    int b = blockIdx.x >> 4;
    int chunk = blockIdx.x & 15;
    int n0 = chunk * 64;
    int tid = threadIdx.x, warp = tid >> 5, lane = tid & 31;

    __shared__ float swr[64], sww[64];
    __shared__ __align__(16) float rbuf[8][128];

    const float* wr = ws + ((size_t)(2 * head) * CB + b) * CN + n0;
    const float* ww = ws + ((size_t)(2 * head + 1) * CB + b) * CN + n0;
    if (tid < 64)        swr[tid] = wr[tid];
    else if (tid < 128)  sww[tid - 64] = ww[tid - 64];

    const float* qrow = Q + b * Q_STRIDE + head * 390;
    float4 e4, a4;
    {
        int m0 = lane * 4;
        e4.x = sigmoidf_(qrow[134 + m0 + 0]);
        e4.y = sigmoidf_(qrow[134 + m0 + 1]);
        e4.z = sigmoidf_(qrow[134 + m0 + 2]);
        e4.w = sigmoidf_(qrow[134 + m0 + 3]);
        a4.x = qrow[262 + m0 + 0];
        a4.y = qrow[262 + m0 + 1];
        a4.z = qrow[262 + m0 + 2];
        a4.w = qrow[262 + m0 + 3];
    }
    float4 kr4 = make_float4(0.f, 0.f, 0.f, 0.f);
    float4 kw4 = make_float4(0.f, 0.f, 0.f, 0.f);
    if (nextHead >= 0) {
        const float* pn = P + b * P_STRIDE + nextHead * 134 + lane * 4;
        const float* qn = Q + b * Q_STRIDE + nextHead * 390 + lane * 4;
        kr4.x = pn[0]; kr4.y = pn[1]; kr4.z = pn[2]; kr4.w = pn[3];
        kw4.x = qn[0]; kw4.y = qn[1]; kw4.z = qn[2]; kw4.w = qn[3];
    }
    __syncthreads();

    float accR0 = 0.f, accR1 = 0.f, accR2 = 0.f, accR3 = 0.f;
    int rowBase = n0 + warp * 8;
    const float4* s = (const float4*)(src + ((size_t)b * CN + rowBase) * CM) + lane;
    float4*       d = (float4*)      (dst + ((size_t)b * CN + rowBase) * CM) + lane;

    #pragma unroll
    for (int r = 0; r < 8; r++) {
        float4 v = s[(size_t)r * 32];
        int rl = warp * 8 + r;
        float wrv = swr[rl], wwv = sww[rl];
        accR0 += wrv * v.x; accR1 += wrv * v.y; accR2 += wrv * v.z; accR3 += wrv * v.w;
        float4 nv;
        nv.x = v.x * (1.f - wwv * e4.x) + wwv * a4.x;
        nv.y = v.y * (1.f - wwv * e4.y) + wwv * a4.y;
        nv.z = v.z * (1.f - wwv * e4.z) + wwv * a4.z;
        nv.w = v.w * (1.f - wwv * e4.w) + wwv * a4.w;
        d[(size_t)r * 32] = nv;
        if (nextHead >= 0) {
            float pr = nv.x * kr4.x + nv.y * kr4.y + nv.z * kr4.z + nv.w * kr4.w;
            float pw = nv.x * kw4.x + nv.y * kw4.y + nv.z * kw4.z + nv.w * kw4.w;
            float pn = nv.x * nv.x + nv.y * nv.y + nv.z * nv.z + nv.w * nv.w;
            pr = warpSum(pr); pw = warpSum(pw); pn = warpSum(pn);
            if (lane == 0) {
                size_t idx = (size_t)b * CN + n0 + rl;
                dot_r[idx] = pr;
                dot_w[idx] = pw;
                rnorm[idx] = sqrtf(pn);
            }
        }
    }

    // block-reduce the read-vector partials across the 8 warps
    rbuf[warp][lane * 4 + 0] = accR0;
    rbuf[warp][lane * 4 + 1] = accR1;
    rbuf[warp][lane * 4 + 2] = accR2;
    rbuf[warp][lane * 4 + 3] = accR3;
    __syncthreads();
    if (tid < 128) {
        float sum = 0.f;
        #pragma unroll
        for (int w = 0; w < 8; w++) sum += rbuf[w][tid];
        partial[((size_t)b * 16 + chunk) * CM + tid] = sum;
    }
}

__global__ void reduce_reads_k(const float* __restrict__ partial, float* __restrict__ reads_out,
                               int head)
{
    int idx = blockIdx.x * blockDim.x + threadIdx.x;
    if (idx >= CB * CM) return;
    int b = idx >> 7, m = idx & 127;
    float s = 0.f;
    #pragma unroll
    for (int c = 0; c < 16; c++) s += partial[((size_t)b * 16 + c) * CM + m];
    reads_out[(size_t)head * CB * CM + idx] = s;
}

// ---------------- launcher ----------------
extern "C" void kernel_launch(void* const* d_in, const int* in_sizes, int n_in,
                              void* d_out, int out_size)
{
    const float* x          = (const float*)d_in[0];
    const float* prev_reads = (const float*)d_in[1];
    const float* h0         = (const float*)d_in[2];
    const float* c0         = (const float*)d_in[3];
    const float* prev_w     = (const float*)d_in[4];
    const float* prev_mem   = (const float*)d_in[5];
    const float* W_ih       = (const float*)d_in[6];
    const float* W_hh       = (const float*)d_in[7];
    const float* b_ih       = (const float*)d_in[8];
    const float* b_hh       = (const float*)d_in[9];
    const float* Wr         = (const float*)d_in[10];
    const float* br         = (const float*)d_in[11];
    const float* Ww         = (const float*)d_in[12];
    const float* bw         = (const float*)d_in[13];
    const float* fc_W       = (const float*)d_in[14];
    const float* fc_b       = (const float*)d_in[15];
    float* out = (float*)d_out;

    float *mem_s, *inp, *inp2, *gates, *P, *Q, *dotr, *dotw, *rnorm, *partial;
    cudaGetSymbolAddress((void**)&mem_s,   g_mem);
    cudaGetSymbolAddress((void**)&inp,     g_inp);
    cudaGetSymbolAddress((void**)&inp2,    g_inp2);
    cudaGetSymbolAddress((void**)&gates,   g_gates);
    cudaGetSymbolAddress((void**)&P,       g_P);
    cudaGetSymbolAddress((void**)&Q,       g_Q);
    cudaGetSymbolAddress((void**)&dotr,    g_dotr);
    cudaGetSymbolAddress((void**)&dotw,    g_dotw);
    cudaGetSymbolAddress((void**)&rnorm,   g_rnorm);
    cudaGetSymbolAddress((void**)&partial, g_partial);

    // output layout: o | mem | reads | new_ws | h | c
    const size_t off_o     = 0;
    const size_t off_mem   = (size_t)CB * 128;
    const size_t off_reads = off_mem + (size_t)CB * CN * CM;
    const size_t off_ws    = off_reads + (size_t)CNH * CB * CM;
    const size_t off_h     = off_ws + (size_t)2 * CNH * CB * CN;
    const size_t off_c     = off_h + (size_t)CB * CH;

    // 1) controller input
    assemble_inp_k<<<(CB * 640 + 255) / 256, 256>>>(x, prev_reads, inp);
    // 2) LSTM gates
    sgemm_k<<<dim3(2048 / TBN, CB / TBM), 128>>>(gates, inp, W_ih, b_ih, CB, 2048, 640, 0, 0);
    sgemm_k<<<dim3(2048 / TBN, CB / TBM), 128>>>(gates, h0,  W_hh, b_hh, CB, 2048, 512, 1, 0);
    // 3) LSTM pointwise -> h (ctrl) and c directly into output slots
    lstm_k<<<(CB * CH + 255) / 256, 256>>>(gates, c0, out + off_h, out + off_c);
    const float* ctrl = out + off_h;
    // 4) all head parameters in two GEMMs
    sgemm_k<<<dim3((P_STRIDE + TBN - 1) / TBN, CB / TBM), 128>>>(P, ctrl, Wr, br, CB, P_STRIDE, 512, 0, 0);
    sgemm_k<<<dim3((Q_STRIDE + TBN - 1) / TBN, CB / TBM), 128>>>(Q, ctrl, Ww, bw, CB, Q_STRIDE, 512, 0, 0);

    // 5) head 0 content dots over prev_mem (only standalone dots pass)
    dots_k<<<CB * (CN / 8), 256>>>(prev_mem, P, Q, dotr, dotw, rnorm, 0);

    // 6) sequential heads; update pass emits dots for head i+1 from register-resident new rows
    for (int i = 0; i < CNH; i++) {
        const float* src = (i == 0) ? prev_mem : mem_s;
        float* dst = (i == 3) ? (out + off_mem) : mem_s;
        int nextHead = (i < 3) ? (i + 1) : -1;
        address_k<<<2 * CB, 256>>>(P, Q, dotr, dotw, rnorm, prev_w, out + off_ws, i);
        update_fused_k<<<CB * 16, 256>>>(src, dst, P, Q, out + off_ws, partial,
                                         dotr, dotw, rnorm, i, nextHead);
        reduce_reads_k<<<(CB * CM + 255) / 256, 256>>>(partial, out + off_reads, i);
    }

    // 7) output head: sigmoid([ctrl | reads] @ fc_W^T + fc_b)
    assemble_inp2_k<<<(CB * 1024 + 255) / 256, 256>>>(ctrl, out + off_reads, inp2);
    sgemm_k<<<dim3(128 / TBN, CB / TBM), 128>>>(out + off_o, inp2, fc_W, fc_b, CB, 128, 1024, 0, 1);

    (void)in_sizes; (void)n_in; (void)out_size;
}

// round 16
// speedup vs baseline: 1.0026x; 1.0026x over previous
#include <cuda_runtime.h>
#include <math.h>

// ---------------- problem constants ----------------
#define CB 512      // batch
#define CN 1024     // memory rows
#define CM 128      // memory width
#define CH 512      // hidden
#define CNH 4       // heads
#define EPSC 1e-16f

#define P_STRIDE 536    // 4 * 134
#define Q_STRIDE 1560   // 4 * 390

// ---------------- scratch (allocation-free) ----------------
__device__ float g_mem[(size_t)CB * CN * CM];   // 268 MB working memory state
__device__ float g_inp[CB * 640];
__device__ float g_inp2[CB * 1024];
__device__ float g_gates[CB * 2048];
__device__ float g_P[CB * P_STRIDE];
__device__ float g_Q[CB * Q_STRIDE];
__device__ float g_dotr[CB * CN];
__device__ float g_dotw[CB * CN];
__device__ float g_rnorm[CB * CN];
__device__ float g_partial[CB * 16 * CM];

// ---------------- device helpers ----------------
__device__ __forceinline__ float sigmoidf_(float x) { return 1.f / (1.f + expf(-x)); }
__device__ __forceinline__ float softplusf_(float x) {
    return fmaxf(x, 0.f) + log1pf(expf(-fabsf(x)));
}
__device__ __forceinline__ float warpSum(float v) {
    #pragma unroll
    for (int o = 16; o; o >>= 1) v += __shfl_xor_sync(0xffffffffu, v, o);
    return v;
}
__device__ __forceinline__ float warpMax(float v) {
    #pragma unroll
    for (int o = 16; o; o >>= 1) v = fmaxf(v, __shfl_xor_sync(0xffffffffu, v, o));
    return v;
}
__device__ float blockSum(float v, float* red) {
    int lane = threadIdx.x & 31, w = threadIdx.x >> 5, nw = (blockDim.x + 31) >> 5;
    v = warpSum(v);
    __syncthreads();
    if (lane == 0) red[w] = v;
    __syncthreads();
    if (w == 0) {
        float t = (lane < nw) ? red[lane] : 0.f;
        t = warpSum(t);
        if (lane == 0) red[0] = t;
    }
    __syncthreads();
    return red[0];
}
__device__ float blockMax(float v, float* red) {
    int lane = threadIdx.x & 31, w = threadIdx.x >> 5, nw = (blockDim.x + 31) >> 5;
    v = warpMax(v);
    __syncthreads();
    if (lane == 0) red[w] = v;
    __syncthreads();
    if (w == 0) {
        float t = (lane < nw) ? red[lane] : -INFINITY;
        t = warpMax(t);
        if (lane == 0) red[0] = t;
    }
    __syncthreads();
    return red[0];
}

// ---------------- generic SGEMM: C[M,N] = A[M,K] @ W[N,K]^T (+bias)(+acc)(+sigmoid) ----------------
#define TBM 64
#define TBN 64
#define TBK 16

__global__ void __launch_bounds__(128) sgemm_k(
    float* __restrict__ C, const float* __restrict__ A, const float* __restrict__ W,
    const float* __restrict__ bias, int M, int N, int K, int accFlag, int actFlag)
{
    __shared__ __align__(16) float As[TBK][TBM + 4];
    __shared__ __align__(16) float Bs[TBK][TBN];
    int tid = threadIdx.x;
    int bm = blockIdx.y * TBM;
    int bn = blockIdx.x * TBN;
    int ty = tid >> 4;
    int tx = tid & 15;
    int row0 = ty * 8;
    int col0 = tx * 4;

    float acc[8][4];
    #pragma unroll
    for (int r = 0; r < 8; r++)
        #pragma unroll
        for (int c = 0; c < 4; c++) acc[r][c] = 0.f;

    for (int k0 = 0; k0 < K; k0 += TBK) {
        #pragma unroll
        for (int l = tid; l < TBM * TBK / 4; l += 128) {
            int r = l >> 2;
            int kk = (l & 3) * 4;
            float4 v = *(const float4*)(A + (size_t)(bm + r) * K + k0 + kk);
            As[kk + 0][r] = v.x; As[kk + 1][r] = v.y; As[kk + 2][r] = v.z; As[kk + 3][r] = v.w;
        }
        #pragma unroll
        for (int l = tid; l < TBN * TBK / 4; l += 128) {
            int r = l >> 2;
            int kk = (l & 3) * 4;
            float4 v = make_float4(0.f, 0.f, 0.f, 0.f);
            if (bn + r < N) v = *(const float4*)(W + (size_t)(bn + r) * K + k0 + kk);
            Bs[kk + 0][r] = v.x; Bs[kk + 1][r] = v.y; Bs[kk + 2][r] = v.z; Bs[kk + 3][r] = v.w;
        }
        __syncthreads();
        #pragma unroll
        for (int kk = 0; kk < TBK; kk++) {
            float4 a0 = *(const float4*)&As[kk][row0];
            float4 a1 = *(const float4*)&As[kk][row0 + 4];
            float4 b0 = *(const float4*)&Bs[kk][col0];
            float ar[8] = {a0.x, a0.y, a0.z, a0.w, a1.x, a1.y, a1.z, a1.w};
            float br_[4] = {b0.x, b0.y, b0.z, b0.w};
            #pragma unroll
            for (int r = 0; r < 8; r++)
                #pragma unroll
                for (int c = 0; c < 4; c++) acc[r][c] += ar[r] * br_[c];
        }
        __syncthreads();
    }
    #pragma unroll
    for (int r = 0; r < 8; r++) {
        int gr = bm + row0 + r;
        #pragma unroll
        for (int c = 0; c < 4; c++) {
            int gc = bn + col0 + c;
            if (gc < N) {
                float v = acc[r][c];
                if (bias) v += bias[gc];
                if (accFlag) v += C[(size_t)gr * N + gc];
                if (actFlag) v = sigmoidf_(v);
                C[(size_t)gr * N + gc] = v;
            }
        }
    }
}

// ---------------- small assembly / pointwise kernels ----------------
__global__ void assemble_inp_k(const float* __restrict__ x, const float* __restrict__ pr,
                               float* __restrict__ inp)
{
    int idx = blockIdx.x * blockDim.x + threadIdx.x;
    if (idx >= CB * 640) return;
    int b = idx / 640, j = idx % 640;
    float v;
    if (j < 128) v = x[b * 128 + j];
    else {
        int jj = j - 128;
        v = pr[((jj >> 7) * CB + b) * CM + (jj & 127)];
    }
    inp[idx] = v;
}

__global__ void lstm_k(const float* __restrict__ gates, const float* __restrict__ c0,
                       float* __restrict__ h_out, float* __restrict__ c_out)
{
    int idx = blockIdx.x * blockDim.x + threadIdx.x;
    if (idx >= CB * CH) return;
    int b = idx / CH, j = idx % CH;
    const float* g = gates + (size_t)b * 2048;
    float ig = g[j], fg = g[512 + j], gg = g[1024 + j], og = g[1536 + j];
    float cn = sigmoidf_(fg) * c0[idx] + sigmoidf_(ig) * tanhf(gg);
    float hn = sigmoidf_(og) * tanhf(cn);
    h_out[idx] = hn;
    c_out[idx] = cn;
}

__global__ void assemble_inp2_k(const float* __restrict__ ctrl, const float* __restrict__ rd,
                                float* __restrict__ inp2)
{
    int idx = blockIdx.x * blockDim.x + threadIdx.x;
    if (idx >= CB * 1024) return;
    int b = idx >> 10, j = idx & 1023;
    float v;
    if (j < 512) v = ctrl[b * 512 + j];
    else {
        int jj = j - 512;
        v = rd[(size_t)(jj >> 7) * CB * CM + b * CM + (jj & 127)];
    }
    inp2[idx] = v;
}

// ---------------- head-0 dots + row norms (one stream over prev_mem) ----------------
__global__ void __launch_bounds__(256) dots_k(
    const float* __restrict__ mem, const float* __restrict__ P, const float* __restrict__ Q,
    float* __restrict__ dot_r, float* __restrict__ dot_w, float* __restrict__ rnorm, int head)
{
    int b = blockIdx.x >> 7;
    int n0 = (blockIdx.x & 127) * 8;
    __shared__ __align__(16) float kr[128];
    __shared__ __align__(16) float kw[128];
    int tid = threadIdx.x;
    if (tid < 128) kr[tid] = P[b * P_STRIDE + head * 134 + tid];
    else           kw[tid - 128] = Q[b * Q_STRIDE + head * 390 + (tid - 128)];
    __syncthreads();
    int warp = tid >> 5, lane = tid & 31;
    int n = n0 + warp;
    const float4* row = (const float4*)(mem + ((size_t)b * CN + n) * CM);
    float4 v = row[lane];
    float4 a = *(const float4*)&kr[lane * 4];
    float4 c = *(const float4*)&kw[lane * 4];
    float dr = v.x * a.x + v.y * a.y + v.z * a.z + v.w * a.w;
    float dw = v.x * c.x + v.y * c.y + v.z * c.z + v.w * c.w;
    float ss = v.x * v.x + v.y * v.y + v.z * v.z + v.w * v.w;
    dr = warpSum(dr); dw = warpSum(dw); ss = warpSum(ss);
    if (lane == 0) {
        size_t idx = (size_t)b * CN + n;
        dot_r[idx] = dr;
        dot_w[idx] = dw;
        rnorm[idx] = sqrtf(ss);
    }
}

// ---------------- addressing: softmax / interp / shift / sharpen ----------------
__global__ void __launch_bounds__(256) address_k(
    const float* __restrict__ P, const float* __restrict__ Q,
    const float* __restrict__ dot_r, const float* __restrict__ dot_w,
    const float* __restrict__ rnorm, const float* __restrict__ prev_w,
    float* __restrict__ ws_out, int head)
{
    int b = blockIdx.x & (CB - 1);
    int rw = blockIdx.x >> 9;
    const float* row = (rw == 0) ? (P + b * P_STRIDE + head * 134)
                                 : (Q + b * Q_STRIDE + head * 390);
    const float* dot = ((rw == 0) ? dot_r : dot_w) + (size_t)b * CN;
    const float* rn  = rnorm + (size_t)b * CN;
    int widx = 2 * head + rw;
    const float* wp = prev_w + (size_t)widx * CB * CN + (size_t)b * CN;
    float* wout = ws_out + (size_t)widx * CB * CN + (size_t)b * CN;

    __shared__ float sh[CN];
    __shared__ float red[32];
    __shared__ float sp[8];
    int tid = threadIdx.x;

    float kk = 0.f;
    if (tid < 128) { float kv = row[tid]; kk = kv * kv; }
    kk = blockSum(kk, red);
    if (tid == 0) {
        sp[0] = fmaxf(sqrtf(kk), EPSC);
        sp[1] = softplusf_(row[128]);          // beta
        sp[2] = sigmoidf_(row[129]);           // g
        float s0r = row[130], s1r = row[131], s2r = row[132];
        float mx = fmaxf(s0r, fmaxf(s1r, s2r));
        float e0 = expf(s0r - mx), e1 = expf(s1r - mx), e2 = expf(s2r - mx);
        float es = e0 + e1 + e2;
        sp[3] = e0 / es; sp[4] = e1 / es; sp[5] = e2 / es;
        sp[6] = 1.f + softplusf_(row[133]);    // gamma
    }
    __syncthreads();
    float knorm = sp[0], beta = sp[1], gg = sp[2];
    float s0 = sp[3], s1 = sp[4], s2 = sp[5], gamma = sp[6];

    float sc[4];
    float lmax = -INFINITY;
    #pragma unroll
    for (int j = 0; j < 4; j++) {
        int n = tid + j * 256;
        float rnv = fmaxf(rn[n], EPSC);
        sc[j] = beta * (dot[n] / (rnv * knorm));
        lmax = fmaxf(lmax, sc[j]);
    }
    float mx = blockMax(lmax, red);
    float lsum = 0.f;
    float ev[4];
    #pragma unroll
    for (int j = 0; j < 4; j++) { ev[j] = expf(sc[j] - mx); lsum += ev[j]; }
    float S = blockSum(lsum, red);
    #pragma unroll
    for (int j = 0; j < 4; j++) {
        int n = tid + j * 256;
        float wc = ev[j] / S;
        sh[n] = gg * wc + (1.f - gg) * wp[n];
    }
    __syncthreads();
    float wv[4];
    float lsum2 = 0.f;
    #pragma unroll
    for (int j = 0; j < 4; j++) {
        int n = tid + j * 256;
        float wh = s0 * sh[(n + CN - 1) & (CN - 1)] + s1 * sh[n] + s2 * sh[(n + 1) & (CN - 1)];
        wv[j] = powf(wh, gamma);
        lsum2 += wv[j];
    }
    float T = blockSum(lsum2, red);
    float inv = 1.f / (T + EPSC);
    #pragma unroll
    for (int j = 0; j < 4; j++) {
        int n = tid + j * 256;
        wout[n] = wv[j] * inv;
    }
}

// ---------------- FUSED: memory erase/add + partial read vector + NEXT-head dots ----------------
// NOTE: all head-parameter loads from P/Q are SCALAR — head*134 / head*390 are
// not multiples of 4, so float4 loads there trap with misaligned address.
__global__ void __launch_bounds__(256) update_fused_k(
    const float* __restrict__ src, float* __restrict__ dst,
    const float* __restrict__ P, const float* __restrict__ Q,
    const float* __restrict__ ws, float* __restrict__ partial,
    float* __restrict__ dot_r, float* __restrict__ dot_w, float* __restrict__ rnorm,
    int head, int nextHead)
{
    // grid: CB*16 blocks, 256 threads = 8 warps, 64 rows per block (8 per warp)
    int b = blockIdx.x >> 4;
    int chunk = blockIdx.x & 15;
    int n0 = chunk * 64;
    int tid = threadIdx.x, warp = tid >> 5, lane = tid & 31;

    __shared__ float swr[64], sww[64];
    __shared__ __align__(16) float rbuf[8][128];

    const float* wr = ws + ((size_t)(2 * head) * CB + b) * CN + n0;
    const float* ww = ws + ((size_t)(2 * head + 1) * CB + b) * CN + n0;
    if (tid < 64)        swr[tid] = wr[tid];
    else if (tid < 128)  sww[tid - 64] = ww[tid - 64];

    const float* qrow = Q + b * Q_STRIDE + head * 390;
    float4 e4, a4;
    {
        int m0 = lane * 4;
        e4.x = sigmoidf_(qrow[134 + m0 + 0]);
        e4.y = sigmoidf_(qrow[134 + m0 + 1]);
        e4.z = sigmoidf_(qrow[134 + m0 + 2]);
        e4.w = sigmoidf_(qrow[134 + m0 + 3]);
        a4.x = qrow[262 + m0 + 0];
        a4.y = qrow[262 + m0 + 1];
        a4.z = qrow[262 + m0 + 2];
        a4.w = qrow[262 + m0 + 3];
    }
    float4 kr4 = make_float4(0.f, 0.f, 0.f, 0.f);
    float4 kw4 = make_float4(0.f, 0.f, 0.f, 0.f);
    if (nextHead >= 0) {
        const float* pn = P + b * P_STRIDE + nextHead * 134 + lane * 4;
        const float* qn = Q + b * Q_STRIDE + nextHead * 390 + lane * 4;
        kr4.x = pn[0]; kr4.y = pn[1]; kr4.z = pn[2]; kr4.w = pn[3];
        kw4.x = qn[0]; kw4.y = qn[1]; kw4.z = qn[2]; kw4.w = qn[3];
    }
    __syncthreads();

    float accR0 = 0.f, accR1 = 0.f, accR2 = 0.f, accR3 = 0.f;
    int rowBase = n0 + warp * 8;
    const float4* s = (const float4*)(src + ((size_t)b * CN + rowBase) * CM) + lane;
    float4*       d = (float4*)      (dst + ((size_t)b * CN + rowBase) * CM) + lane;

    #pragma unroll
    for (int r = 0; r < 8; r++) {
        float4 v = s[(size_t)r * 32];
        int rl = warp * 8 + r;
        float wrv = swr[rl], wwv = sww[rl];
        accR0 += wrv * v.x; accR1 += wrv * v.y; accR2 += wrv * v.z; accR3 += wrv * v.w;
        float4 nv;
        nv.x = v.x * (1.f - wwv * e4.x) + wwv * a4.x;
        nv.y = v.y * (1.f - wwv * e4.y) + wwv * a4.y;
        nv.z = v.z * (1.f - wwv * e4.z) + wwv * a4.z;
        nv.w = v.w * (1.f - wwv * e4.w) + wwv * a4.w;
        d[(size_t)r * 32] = nv;
        if (nextHead >= 0) {
            float pr = nv.x * kr4.x + nv.y * kr4.y + nv.z * kr4.z + nv.w * kr4.w;
            float pw = nv.x * kw4.x + nv.y * kw4.y + nv.z * kw4.z + nv.w * kw4.w;
            float pn = nv.x * nv.x + nv.y * nv.y + nv.z * nv.z + nv.w * nv.w;
            pr = warpSum(pr); pw = warpSum(pw); pn = warpSum(pn);
            if (lane == 0) {
                size_t idx = (size_t)b * CN + n0 + rl;
                dot_r[idx] = pr;
                dot_w[idx] = pw;
                rnorm[idx] = sqrtf(pn);
            }
        }
    }

    // block-reduce the read-vector partials across the 8 warps
    rbuf[warp][lane * 4 + 0] = accR0;
    rbuf[warp][lane * 4 + 1] = accR1;
    rbuf[warp][lane * 4 + 2] = accR2;
    rbuf[warp][lane * 4 + 3] = accR3;
    __syncthreads();
    if (tid < 128) {
        float sum = 0.f;
        #pragma unroll
        for (int w = 0; w < 8; w++) sum += rbuf[w][tid];
        partial[((size_t)b * 16 + chunk) * CM + tid] = sum;
    }
}

__global__ void reduce_reads_k(const float* __restrict__ partial, float* __restrict__ reads_out,
                               int head)
{
    int idx = blockIdx.x * blockDim.x + threadIdx.x;
    if (idx >= CB * CM) return;
    int b = idx >> 7, m = idx & 127;
    float s = 0.f;
    #pragma unroll
    for (int c = 0; c < 16; c++) s += partial[((size_t)b * 16 + c) * CM + m];
    reads_out[(size_t)head * CB * CM + idx] = s;
}

// ---------------- launcher ----------------
extern "C" void kernel_launch(void* const* d_in, const int* in_sizes, int n_in,
                              void* d_out, int out_size)
{
    const float* x          = (const float*)d_in[0];
    const float* prev_reads = (const float*)d_in[1];
    const float* h0         = (const float*)d_in[2];
    const float* c0         = (const float*)d_in[3];
    const float* prev_w     = (const float*)d_in[4];
    const float* prev_mem   = (const float*)d_in[5];
    const float* W_ih       = (const float*)d_in[6];
    const float* W_hh       = (const float*)d_in[7];
    const float* b_ih       = (const float*)d_in[8];
    const float* b_hh       = (const float*)d_in[9];
    const float* Wr         = (const float*)d_in[10];
    const float* br         = (const float*)d_in[11];
    const float* Ww         = (const float*)d_in[12];
    const float* bw         = (const float*)d_in[13];
    const float* fc_W       = (const float*)d_in[14];
    const float* fc_b       = (const float*)d_in[15];
    float* out = (float*)d_out;

    float *mem_s, *inp, *inp2, *gates, *P, *Q, *dotr, *dotw, *rnorm, *partial;
    cudaGetSymbolAddress((void**)&mem_s,   g_mem);
    cudaGetSymbolAddress((void**)&inp,     g_inp);
    cudaGetSymbolAddress((void**)&inp2,    g_inp2);
    cudaGetSymbolAddress((void**)&gates,   g_gates);
    cudaGetSymbolAddress((void**)&P,       g_P);
    cudaGetSymbolAddress((void**)&Q,       g_Q);
    cudaGetSymbolAddress((void**)&dotr,    g_dotr);
    cudaGetSymbolAddress((void**)&dotw,    g_dotw);
    cudaGetSymbolAddress((void**)&rnorm,   g_rnorm);
    cudaGetSymbolAddress((void**)&partial, g_partial);

    // output layout: o | mem | reads | new_ws | h | c
    const size_t off_o     = 0;
    const size_t off_mem   = (size_t)CB * 128;
    const size_t off_reads = off_mem + (size_t)CB * CN * CM;
    const size_t off_ws    = off_reads + (size_t)CNH * CB * CM;
    const size_t off_h     = off_ws + (size_t)2 * CNH * CB * CN;
    const size_t off_c     = off_h + (size_t)CB * CH;

    // 1) controller input
    assemble_inp_k<<<(CB * 640 + 255) / 256, 256>>>(x, prev_reads, inp);
    // 2) LSTM gates
    sgemm_k<<<dim3(2048 / TBN, CB / TBM), 128>>>(gates, inp, W_ih, b_ih, CB, 2048, 640, 0, 0);
    sgemm_k<<<dim3(2048 / TBN, CB / TBM), 128>>>(gates, h0,  W_hh, b_hh, CB, 2048, 512, 1, 0);
    // 3) LSTM pointwise -> h (ctrl) and c directly into output slots
    lstm_k<<<(CB * CH + 255) / 256, 256>>>(gates, c0, out + off_h, out + off_c);
    const float* ctrl = out + off_h;
    // 4) all head parameters in two GEMMs
    sgemm_k<<<dim3((P_STRIDE + TBN - 1) / TBN, CB / TBM), 128>>>(P, ctrl, Wr, br, CB, P_STRIDE, 512, 0, 0);
    sgemm_k<<<dim3((Q_STRIDE + TBN - 1) / TBN, CB / TBM), 128>>>(Q, ctrl, Ww, bw, CB, Q_STRIDE, 512, 0, 0);

    // 5) head 0 content dots over prev_mem (only standalone dots pass)
    dots_k<<<CB * (CN / 8), 256>>>(prev_mem, P, Q, dotr, dotw, rnorm, 0);

    // 6) sequential heads; update pass emits dots for head i+1 from register-resident new rows
    for (int i = 0; i < CNH; i++) {
        const float* src = (i == 0) ? prev_mem : mem_s;
        float* dst = (i == 3) ? (out + off_mem) : mem_s;
        int nextHead = (i < 3) ? (i + 1) : -1;
        address_k<<<2 * CB, 256>>>(P, Q, dotr, dotw, rnorm, prev_w, out + off_ws, i);
        update_fused_k<<<CB * 16, 256>>>(src, dst, P, Q, out + off_ws, partial,
                                         dotr, dotw, rnorm, i, nextHead);
        reduce_reads_k<<<(CB * CM + 255) / 256, 256>>>(partial, out + off_reads, i);
    }

    // 7) output head: sigmoid([ctrl | reads] @ fc_W^T + fc_b)
    assemble_inp2_k<<<(CB * 1024 + 255) / 256, 256>>>(ctrl, out + off_reads, inp2);
    sgemm_k<<<dim3(128 / TBN, CB / TBM), 128>>>(out + off_o, inp2, fc_W, fc_b, CB, 128, 1024, 0, 1);

    (void)in_sizes; (void)n_in; (void)out_size;
}